// round 7
// baseline (speedup 1.0000x reference)
#include <cuda_runtime.h>
#include <cuda_fp16.h>
#include <cuda_bf16.h>

#define NTOKEN 150000
#define NINP   64
#define NEDGE  2400000
#define NBL    12800
#define BMWORDS ((NTOKEN + 31) / 32)
#define NB_SCAN ((NTOKEN + 255) / 256)   // 586 scan blocks; 586*8 == BMWORDS

// ---------------------------------------------------------------------------
// Scratch
// ---------------------------------------------------------------------------
__device__ __align__(16) float g_y[NTOKEN * NINP];
__device__ __align__(16) float g_z[NTOKEN * NINP];
__device__ __align__(16) __half g_xh[NTOKEN * NINP];  // fp16 copy of X
__device__ int      g_deg[NTOKEN];
__device__ float    g_dinv[NTOKEN];
__device__ float    g_c[NTOKEN];
__device__ unsigned g_tokbm[BMWORDS];
__device__ unsigned g_bmneed[BMWORDS];
__device__ __align__(16) int2 g_ce[NEDGE];           // stashed (s,d)
__device__ int      g_off[NTOKEN];
__device__ int      g_cur[NTOKEN];
__device__ int      g_csr[NEDGE];
__device__ int      g_bsum[NB_SCAN];
__device__ int      g_bbase[NB_SCAN];
__device__ int      g_toklist[NBL];
__device__ int      g_ntok;
__device__ int      g_needlist[NTOKEN];
__device__ int      g_nneed;
__device__ float    g_W12[NINP * NINP];
__device__ float    g_bW[NINP];
__device__ int      g_is64;

// ---------------------------------------------------------------------------
__device__ __forceinline__ long long ld_idx(const void* p, long long i, int is64) {
    return is64 ? ((const long long*)p)[i] : (long long)((const int*)p)[i];
}

// K1: zero small state + int64/int32 detection (thread 0)
__global__ void k_zero(const void* __restrict__ eidx) {
    int i = blockIdx.x * blockDim.x + threadIdx.x;
    if (i < NTOKEN) g_deg[i] = 0;
    if (i < BMWORDS) { g_tokbm[i] = 0u; g_bmneed[i] = 0u; }
    if (i == 0) {
        g_ntok = 0; g_nneed = 0;
        const long long* p = (const long long*)eidx;
        int ok = 1;
        #pragma unroll
        for (int k = 0; k < 16; k++) {
            long long v = p[k];
            if (v < 0 || v >= NTOKEN) ok = 0;
        }
        g_is64 = ok;
    }
}

// K1b: X -> fp16 copy
__global__ void k_x2h(const float* __restrict__ X) {
    int i = blockIdx.x * blockDim.x + threadIdx.x;
    const int N4 = NTOKEN * NINP / 4;                // 2.4M
    if (i >= N4) return;
    float4 v = __ldg(((const float4*)X) + i);
    ((__half2*)g_xh)[i * 2]     = __floats2half2_rn(v.x, v.y);
    ((__half2*)g_xh)[i * 2 + 1] = __floats2half2_rn(v.z, v.w);
}

// K2: token bitmap + unique-token list + bmneed(token)
__global__ void k_tokbm(const void* __restrict__ inp) {
    int i = blockIdx.x * blockDim.x + threadIdx.x;
    if (i >= NBL) return;
    int t = (int)ld_idx(inp, i, g_is64);
    unsigned bit = 1u << (t & 31);
    unsigned old = atomicOr(&g_tokbm[t >> 5], bit);
    if (!(old & bit)) g_toklist[atomicAdd(&g_ntok, 1)] = t;
    atomicOr(&g_bmneed[t >> 5], bit);
}

// K3: decode+stash edges, degree count, bmneed(src of token-dst edges)
__global__ void k_deg(const void* __restrict__ eidx) {
    int e = blockIdx.x * blockDim.x + threadIdx.x;
    if (e >= NEDGE) return;
    int is64 = g_is64;
    int s = (int)ld_idx(eidx, e, is64);
    int d = (int)ld_idx(eidx, (long long)NEDGE + e, is64);
    g_ce[e] = make_int2(s, d);
    atomicAdd(&g_deg[d], 1);
    if ((g_tokbm[d >> 5] >> (d & 31)) & 1u)
        atomicOr(&g_bmneed[s >> 5], 1u << (s & 31));
}

// K4a: per-block degree sums
__global__ void k_bsum() {
    __shared__ int sm[256];
    int i = blockIdx.x * 256 + threadIdx.x;
    int v = (i < NTOKEN) ? g_deg[i] : 0;
    sm[threadIdx.x] = v;
    __syncthreads();
    for (int off = 128; off > 0; off >>= 1) {
        if (threadIdx.x < off) sm[threadIdx.x] += sm[threadIdx.x + off];
        __syncthreads();
    }
    if (threadIdx.x == 0) g_bsum[blockIdx.x] = sm[0];
}

// K4b: exclusive scan of block sums. <<<1,1024>>>
__global__ void k_btop() {
    __shared__ int sm[1024];
    int t = threadIdx.x;
    int v = (t < NB_SCAN) ? g_bsum[t] : 0;
    sm[t] = v;
    __syncthreads();
    for (int off = 1; off < 1024; off <<= 1) {
        int u = (t >= off) ? sm[t - off] : 0;
        __syncthreads();
        sm[t] += u;
        __syncthreads();
    }
    if (t < NB_SCAN) g_bbase[t] = sm[t] - v;
}

// K4c: per-block scan + base -> off/cur; fused dinv; fused needlist compaction
__global__ void k_offs() {
    __shared__ int sm[256];
    int t = threadIdx.x;
    int i = blockIdx.x * 256 + t;
    int d = (i < NTOKEN) ? g_deg[i] : 0;
    sm[t] = d;
    __syncthreads();
    for (int off = 1; off < 256; off <<= 1) {
        int u = (t >= off) ? sm[t - off] : 0;
        __syncthreads();
        sm[t] += u;
        __syncthreads();
    }
    if (i < NTOKEN) {
        int o = g_bbase[blockIdx.x] + sm[t] - d;
        g_off[i] = o;
        g_cur[i] = o;
        g_dinv[i] = rsqrtf((float)d + 1.0f);
    }
    if (t < 8) {
        int wi = blockIdx.x * 8 + t;
        if (wi < BMWORDS) {
            unsigned w = g_bmneed[wi];
            if (w) {
                int base = atomicAdd(&g_nneed, __popc(w));
                while (w) {
                    int b = __ffs(w) - 1;
                    g_needlist[base++] = wi * 32 + b;
                    w &= w - 1u;
                }
            }
        }
    }
}

// K5: fill CSR, only for dst in bmneed; 2 edges/thread via int4
__global__ void k_fill() {
    int t = blockIdx.x * blockDim.x + threadIdx.x;
    int e = t * 2;
    if (e >= NEDGE) return;
    int4 p = *(const int4*)&g_ce[e];                 // (s0,d0,s1,d1)
    if ((g_bmneed[p.y >> 5] >> (p.y & 31)) & 1u) {
        int pos = atomicAdd(&g_cur[p.y], 1);
        g_csr[pos] = p.x;
    }
    if ((g_bmneed[p.w >> 5] >> (p.w & 31)) & 1u) {
        int pos = atomicAdd(&g_cur[p.w], 1);
        g_csr[pos] = p.z;
    }
}

// K7: gather pass 1 — warp per needed node; neighbor reads in fp16, self in fp32
__global__ void k_gather1(const float* __restrict__ X) {
    int w = (int)(((long long)blockIdx.x * blockDim.x + threadIdx.x) >> 5);
    if (w >= g_nneed) return;
    int d = g_needlist[w];
    int lane = threadIdx.x & 31;
    int beg = g_off[d], end = g_cur[d];
    float dd = g_dinv[d];
    float ax = 0.f, ay = 0.f;
    int i = beg;
    for (; i + 8 <= end; i += 8) {
        int s0 = __ldg(&g_csr[i]),     s1 = __ldg(&g_csr[i + 1]);
        int s2 = __ldg(&g_csr[i + 2]), s3 = __ldg(&g_csr[i + 3]);
        int s4 = __ldg(&g_csr[i + 4]), s5 = __ldg(&g_csr[i + 5]);
        int s6 = __ldg(&g_csr[i + 6]), s7 = __ldg(&g_csr[i + 7]);
        float w0 = __ldg(&g_dinv[s0]), w1 = __ldg(&g_dinv[s1]);
        float w2 = __ldg(&g_dinv[s2]), w3 = __ldg(&g_dinv[s3]);
        float w4 = __ldg(&g_dinv[s4]), w5 = __ldg(&g_dinv[s5]);
        float w6 = __ldg(&g_dinv[s6]), w7 = __ldg(&g_dinv[s7]);
        float2 x0 = __half22float2(__ldg(((const __half2*)(g_xh + s0 * NINP)) + lane));
        float2 x1 = __half22float2(__ldg(((const __half2*)(g_xh + s1 * NINP)) + lane));
        float2 x2 = __half22float2(__ldg(((const __half2*)(g_xh + s2 * NINP)) + lane));
        float2 x3 = __half22float2(__ldg(((const __half2*)(g_xh + s3 * NINP)) + lane));
        float2 x4 = __half22float2(__ldg(((const __half2*)(g_xh + s4 * NINP)) + lane));
        float2 x5 = __half22float2(__ldg(((const __half2*)(g_xh + s5 * NINP)) + lane));
        float2 x6 = __half22float2(__ldg(((const __half2*)(g_xh + s6 * NINP)) + lane));
        float2 x7 = __half22float2(__ldg(((const __half2*)(g_xh + s7 * NINP)) + lane));
        ax += w0 * x0.x + w1 * x1.x + w2 * x2.x + w3 * x3.x
            + w4 * x4.x + w5 * x5.x + w6 * x6.x + w7 * x7.x;
        ay += w0 * x0.y + w1 * x1.y + w2 * x2.y + w3 * x3.y
            + w4 * x4.y + w5 * x5.y + w6 * x6.y + w7 * x7.y;
    }
    for (; i + 4 <= end; i += 4) {
        int s0 = __ldg(&g_csr[i]),     s1 = __ldg(&g_csr[i + 1]);
        int s2 = __ldg(&g_csr[i + 2]), s3 = __ldg(&g_csr[i + 3]);
        float w0 = __ldg(&g_dinv[s0]), w1 = __ldg(&g_dinv[s1]);
        float w2 = __ldg(&g_dinv[s2]), w3 = __ldg(&g_dinv[s3]);
        float2 x0 = __half22float2(__ldg(((const __half2*)(g_xh + s0 * NINP)) + lane));
        float2 x1 = __half22float2(__ldg(((const __half2*)(g_xh + s1 * NINP)) + lane));
        float2 x2 = __half22float2(__ldg(((const __half2*)(g_xh + s2 * NINP)) + lane));
        float2 x3 = __half22float2(__ldg(((const __half2*)(g_xh + s3 * NINP)) + lane));
        ax += w0 * x0.x + w1 * x1.x + w2 * x2.x + w3 * x3.x;
        ay += w0 * x0.y + w1 * x1.y + w2 * x2.y + w3 * x3.y;
    }
    for (; i < end; i++) {
        int s = __ldg(&g_csr[i]);
        float ww = __ldg(&g_dinv[s]);
        float2 x = __half22float2(__ldg(((const __half2*)(g_xh + s * NINP)) + lane));
        ax += ww * x.x; ay += ww * x.y;
    }
    ax *= dd; ay *= dd;
    float2 xs = __ldg(((const float2*)(X + d * NINP)) + lane);  // self term fp32
    float sw = dd * dd;
    ax += sw * xs.x; ay += sw * xs.y;
    ((float2*)(g_y + d * NINP))[lane] = make_float2(ax, ay);
}

// K8: gather pass 2 — warp per unique token node (fp32 y)
__global__ void k_gather2() {
    int w = (int)(((long long)blockIdx.x * blockDim.x + threadIdx.x) >> 5);
    if (w >= g_ntok) return;
    int d = g_toklist[w];
    int lane = threadIdx.x & 31;
    int beg = g_off[d], end = g_cur[d];
    float dd = g_dinv[d];
    float ax = 0.f, ay = 0.f, cw = 0.f;
    int i = beg;
    for (; i + 4 <= end; i += 4) {
        int s0 = __ldg(&g_csr[i]),     s1 = __ldg(&g_csr[i + 1]);
        int s2 = __ldg(&g_csr[i + 2]), s3 = __ldg(&g_csr[i + 3]);
        float w0 = __ldg(&g_dinv[s0]), w1 = __ldg(&g_dinv[s1]);
        float w2 = __ldg(&g_dinv[s2]), w3 = __ldg(&g_dinv[s3]);
        float2 x0 = ((const float2*)(g_y + s0 * NINP))[lane];
        float2 x1 = ((const float2*)(g_y + s1 * NINP))[lane];
        float2 x2 = ((const float2*)(g_y + s2 * NINP))[lane];
        float2 x3 = ((const float2*)(g_y + s3 * NINP))[lane];
        ax += w0 * x0.x + w1 * x1.x + w2 * x2.x + w3 * x3.x;
        ay += w0 * x0.y + w1 * x1.y + w2 * x2.y + w3 * x3.y;
        cw += w0 + w1 + w2 + w3;
    }
    for (; i < end; i++) {
        int s = __ldg(&g_csr[i]);
        float ww = __ldg(&g_dinv[s]);
        float2 x = ((const float2*)(g_y + s * NINP))[lane];
        ax += ww * x.x; ay += ww * x.y; cw += ww;
    }
    ax *= dd; ay *= dd; cw *= dd;
    float sw = dd * dd;
    float2 ys = ((const float2*)(g_y + d * NINP))[lane];
    ax += sw * ys.x; ay += sw * ys.y; cw += sw;
    ((float2*)(g_z + d * NINP))[lane] = make_float2(ax, ay);
    if (lane == 0) g_c[d] = cw;
}

// K9: W12 = W1@W2, bW = b1@W2
__global__ void k_w12(const float* __restrict__ W1, const float* __restrict__ b1,
                      const float* __restrict__ W2) {
    int j = threadIdx.x;
    int b = blockIdx.x;
    float acc = 0.f;
    if (b < NINP) {
        #pragma unroll 8
        for (int k = 0; k < 2 * NINP; k++) acc += W1[b * 2 * NINP + k] * W2[k * NINP + j];
        g_W12[b * NINP + j] = acc;
    } else {
        #pragma unroll 8
        for (int k = 0; k < 2 * NINP; k++) acc += b1[k] * W2[k * NINP + j];
        g_bW[j] = acc;
    }
}

// K10: out[n,j] = z[tok].W12[:,j] + c[tok]*bW[j] + b2[j]
__global__ void k_out(const void* __restrict__ inp, const float* __restrict__ b2,
                      float* __restrict__ out) {
    __shared__ float sW[NINP * NINP];
    __shared__ float sz[4][NINP];
    __shared__ float sc[4];
    int tid = threadIdx.x;
    int g = tid >> 6;
    int j = tid & 63;
    int n = blockIdx.x * 4 + g;
    int is64 = g_is64;

    for (int i = tid; i < NINP * NINP; i += 256) sW[i] = g_W12[i];
    int tok = (int)ld_idx(inp, n, is64);
    sz[g][j] = g_z[tok * NINP + j];
    if (j == 0) sc[g] = g_c[tok];
    __syncthreads();

    float acc = 0.f;
    #pragma unroll
    for (int i = 0; i < NINP; i++) acc += sz[g][i] * sW[i * NINP + j];
    out[n * NINP + j] = acc + sc[g] * g_bW[j] + b2[j];
}

// ---------------------------------------------------------------------------
extern "C" void kernel_launch(void* const* d_in, const int* in_sizes, int n_in,
                              void* d_out, int out_size) {
    const float* emb = (const float*)d_in[0];
    const float* W1  = (const float*)d_in[1];
    const float* b1  = (const float*)d_in[2];
    const float* W2  = (const float*)d_in[3];
    const float* b2  = (const float*)d_in[4];
    const void*  inp = d_in[5];
    const void*  eidx = d_in[7];
    float* out = (float*)d_out;

    const int TB = 256;
    k_zero<<<(NTOKEN + TB - 1) / TB, TB>>>(eidx);
    k_x2h<<<(NTOKEN * NINP / 4 + TB - 1) / TB, TB>>>(emb);
    k_tokbm<<<(NBL + TB - 1) / TB, TB>>>(inp);
    k_deg<<<(NEDGE + TB - 1) / TB, TB>>>(eidx);
    k_bsum<<<NB_SCAN, 256>>>();
    k_btop<<<1, 1024>>>();
    k_offs<<<NB_SCAN, 256>>>();
    k_fill<<<(NEDGE / 2 + TB - 1) / TB, TB>>>();
    k_gather1<<<(NTOKEN * 32 + TB - 1) / TB, TB>>>(emb);
    k_gather2<<<(NBL * 32 + TB - 1) / TB, TB>>>();
    k_w12<<<NINP + 1, NINP>>>(W1, b1, W2);
    k_out<<<NBL / 4, TB>>>(inp, b2, out);
}

// round 8
// speedup vs baseline: 1.0002x; 1.0002x over previous
#include <cuda_runtime.h>
#include <cuda_bf16.h>

#define NTOKEN 150000
#define NINP   64
#define NEDGE  2400000
#define NBL    12800
#define BMWORDS ((NTOKEN + 31) / 32)
#define NB_SCAN ((NTOKEN + 255) / 256)   // 586 scan blocks; 586*8 == BMWORDS

// ---------------------------------------------------------------------------
// Scratch
// ---------------------------------------------------------------------------
__device__ __align__(16) float g_y[NTOKEN * NINP];
__device__ __align__(16) float g_z[NTOKEN * NINP];
__device__ int      g_deg[NTOKEN];
__device__ float    g_dinv[NTOKEN];
__device__ float    g_c[NTOKEN];
__device__ unsigned g_tokbm[BMWORDS];
__device__ unsigned g_bmneed[BMWORDS];
__device__ __align__(16) int2 g_ce[NEDGE];           // stash (is64 path only)
__device__ int      g_off[NTOKEN];
__device__ int      g_cur[NTOKEN];
__device__ __align__(16) int2 g_csrp[NEDGE];         // packed (src, dinv_bits)
__device__ int      g_bsum[NB_SCAN];
__device__ int      g_bbase[NB_SCAN];
__device__ int      g_toklist[NBL];
__device__ int      g_ntok;
__device__ int      g_needlist[NTOKEN];
__device__ int      g_nneed;
__device__ float    g_W12[NINP * NINP];
__device__ float    g_bW[NINP];
__device__ int      g_is64;

// ---------------------------------------------------------------------------
__device__ __forceinline__ long long ld_idx(const void* p, long long i, int is64) {
    return is64 ? ((const long long*)p)[i] : (long long)((const int*)p)[i];
}

// K1: zero small state + int64/int32 detection (thread 0)
__global__ void k_zero(const void* __restrict__ eidx) {
    int i = blockIdx.x * blockDim.x + threadIdx.x;
    if (i < NTOKEN) g_deg[i] = 0;
    if (i < BMWORDS) { g_tokbm[i] = 0u; g_bmneed[i] = 0u; }
    if (i == 0) {
        g_ntok = 0; g_nneed = 0;
        const long long* p = (const long long*)eidx;
        int ok = 1;
        #pragma unroll
        for (int k = 0; k < 16; k++) {
            long long v = p[k];
            if (v < 0 || v >= NTOKEN) ok = 0;
        }
        g_is64 = ok;
    }
}

// K2: token bitmap + unique-token list + bmneed(token)
__global__ void k_tokbm(const void* __restrict__ inp) {
    int i = blockIdx.x * blockDim.x + threadIdx.x;
    if (i >= NBL) return;
    int t = (int)ld_idx(inp, i, g_is64);
    unsigned bit = 1u << (t & 31);
    unsigned old = atomicOr(&g_tokbm[t >> 5], bit);
    if (!(old & bit)) g_toklist[atomicAdd(&g_ntok, 1)] = t;
    atomicOr(&g_bmneed[t >> 5], bit);
}

// K3: degree count + bmneed(src of token-dst edges).
//     int32 path: direct vectorized eidx reads (4 edges/thread), no stash.
//     int64 path: decode + stash to g_ce.
__global__ void k_deg(const void* __restrict__ eidx) {
    int t = blockIdx.x * blockDim.x + threadIdx.x;
    if (g_is64) {
        int e0 = t * 4;
        if (e0 >= NEDGE) return;
        const long long* p = (const long long*)eidx;
        #pragma unroll
        for (int k = 0; k < 4; k++) {
            int e = e0 + k;
            int s = (int)p[e];
            int d = (int)p[(long long)NEDGE + e];
            g_ce[e] = make_int2(s, d);
            atomicAdd(&g_deg[d], 1);
            if ((g_tokbm[d >> 5] >> (d & 31)) & 1u)
                atomicOr(&g_bmneed[s >> 5], 1u << (s & 31));
        }
    } else {
        int e0 = t * 4;
        if (e0 >= NEDGE) return;
        const int* p = (const int*)eidx;
        int4 s4 = __ldg((const int4*)p + t);
        int4 d4 = __ldg((const int4*)(p + NEDGE) + t);
        int ss[4] = {s4.x, s4.y, s4.z, s4.w};
        int dd[4] = {d4.x, d4.y, d4.z, d4.w};
        #pragma unroll
        for (int k = 0; k < 4; k++) {
            int s = ss[k], d = dd[k];
            atomicAdd(&g_deg[d], 1);
            if ((g_tokbm[d >> 5] >> (d & 31)) & 1u)
                atomicOr(&g_bmneed[s >> 5], 1u << (s & 31));
        }
    }
}

// K4a: per-block degree sums
__global__ void k_bsum() {
    __shared__ int sm[256];
    int i = blockIdx.x * 256 + threadIdx.x;
    int v = (i < NTOKEN) ? g_deg[i] : 0;
    sm[threadIdx.x] = v;
    __syncthreads();
    for (int off = 128; off > 0; off >>= 1) {
        if (threadIdx.x < off) sm[threadIdx.x] += sm[threadIdx.x + off];
        __syncthreads();
    }
    if (threadIdx.x == 0) g_bsum[blockIdx.x] = sm[0];
}

// K4b: exclusive scan of block sums. <<<1,1024>>>
__global__ void k_btop() {
    __shared__ int sm[1024];
    int t = threadIdx.x;
    int v = (t < NB_SCAN) ? g_bsum[t] : 0;
    sm[t] = v;
    __syncthreads();
    for (int off = 1; off < 1024; off <<= 1) {
        int u = (t >= off) ? sm[t - off] : 0;
        __syncthreads();
        sm[t] += u;
        __syncthreads();
    }
    if (t < NB_SCAN) g_bbase[t] = sm[t] - v;
}

// K4c: per-block scan + base -> off/cur; fused dinv; fused needlist compaction
__global__ void k_offs() {
    __shared__ int sm[256];
    int t = threadIdx.x;
    int i = blockIdx.x * 256 + t;
    int d = (i < NTOKEN) ? g_deg[i] : 0;
    sm[t] = d;
    __syncthreads();
    for (int off = 1; off < 256; off <<= 1) {
        int u = (t >= off) ? sm[t - off] : 0;
        __syncthreads();
        sm[t] += u;
        __syncthreads();
    }
    if (i < NTOKEN) {
        int o = g_bbase[blockIdx.x] + sm[t] - d;
        g_off[i] = o;
        g_cur[i] = o;
        g_dinv[i] = rsqrtf((float)d + 1.0f);
    }
    if (t < 8) {
        int wi = blockIdx.x * 8 + t;
        if (wi < BMWORDS) {
            unsigned w = g_bmneed[wi];
            if (w) {
                int base = atomicAdd(&g_nneed, __popc(w));
                while (w) {
                    int b = __ffs(w) - 1;
                    g_needlist[base++] = wi * 32 + b;
                    w &= w - 1u;
                }
            }
        }
    }
}

// K5: fill packed CSR (src, dinv[src]) for dst in bmneed
__global__ void k_fill(const void* __restrict__ eidx) {
    int t = blockIdx.x * blockDim.x + threadIdx.x;
    int e0 = t * 4;
    if (e0 >= NEDGE) return;
    int ss[4], dd[4];
    if (g_is64) {
        #pragma unroll
        for (int k = 0; k < 4; k++) {
            int2 sd = g_ce[e0 + k];
            ss[k] = sd.x; dd[k] = sd.y;
        }
    } else {
        const int* p = (const int*)eidx;
        int4 s4 = __ldg((const int4*)p + t);
        int4 d4 = __ldg((const int4*)(p + NEDGE) + t);
        ss[0] = s4.x; ss[1] = s4.y; ss[2] = s4.z; ss[3] = s4.w;
        dd[0] = d4.x; dd[1] = d4.y; dd[2] = d4.z; dd[3] = d4.w;
    }
    #pragma unroll
    for (int k = 0; k < 4; k++) {
        int s = ss[k], d = dd[k];
        if ((g_bmneed[d >> 5] >> (d & 31)) & 1u) {
            int pos = atomicAdd(&g_cur[d], 1);
            g_csrp[pos] = make_int2(s, __float_as_int(__ldg(&g_dinv[s])));
        }
    }
}

// K7: gather pass 1 — warp per needed node, 2 edges per warp-instruction.
//     Lane layout: h = lane>>4 selects edge within pair, q = lane&15 selects
//     4 columns (float4). Final shfl_xor(16) combines the halves.
__global__ void k_gather1(const float* __restrict__ X) {
    int w = (int)(((long long)blockIdx.x * blockDim.x + threadIdx.x) >> 5);
    if (w >= g_nneed) return;
    int d = g_needlist[w];
    int lane = threadIdx.x & 31;
    int h = lane >> 4;
    int q = lane & 15;
    int beg = g_off[d], end = g_cur[d];
    float dd = g_dinv[d];
    float4 acc = make_float4(0.f, 0.f, 0.f, 0.f);
    int i = beg;
    // alignment: make i even so int4 loads of g_csrp are 16B-aligned
    if (i < end && (i & 1)) {
        int2 e1 = __ldg(&g_csrp[i]);
        if (h == 0) {
            float wt = __int_as_float(e1.y);
            float4 x = __ldg(((const float4*)(X + e1.x * NINP)) + q);
            acc.x += wt * x.x; acc.y += wt * x.y; acc.z += wt * x.z; acc.w += wt * x.w;
        }
        i++;
    }
    for (; i + 8 <= end; i += 8) {
        int4 p0 = __ldg((const int4*)&g_csrp[i]);
        int4 p1 = __ldg((const int4*)&g_csrp[i + 2]);
        int4 p2 = __ldg((const int4*)&g_csrp[i + 4]);
        int4 p3 = __ldg((const int4*)&g_csrp[i + 6]);
        int   s0 = h ? p0.z : p0.x;  float w0 = __int_as_float(h ? p0.w : p0.y);
        int   s1 = h ? p1.z : p1.x;  float w1 = __int_as_float(h ? p1.w : p1.y);
        int   s2 = h ? p2.z : p2.x;  float w2 = __int_as_float(h ? p2.w : p2.y);
        int   s3 = h ? p3.z : p3.x;  float w3 = __int_as_float(h ? p3.w : p3.y);
        float4 x0 = __ldg(((const float4*)(X + s0 * NINP)) + q);
        float4 x1 = __ldg(((const float4*)(X + s1 * NINP)) + q);
        float4 x2 = __ldg(((const float4*)(X + s2 * NINP)) + q);
        float4 x3 = __ldg(((const float4*)(X + s3 * NINP)) + q);
        acc.x += w0 * x0.x + w1 * x1.x + w2 * x2.x + w3 * x3.x;
        acc.y += w0 * x0.y + w1 * x1.y + w2 * x2.y + w3 * x3.y;
        acc.z += w0 * x0.z + w1 * x1.z + w2 * x2.z + w3 * x3.z;
        acc.w += w0 * x0.w + w1 * x1.w + w2 * x2.w + w3 * x3.w;
    }
    for (; i + 2 <= end; i += 2) {
        int4 p0 = __ldg((const int4*)&g_csrp[i]);
        int   s0 = h ? p0.z : p0.x;  float w0 = __int_as_float(h ? p0.w : p0.y);
        float4 x0 = __ldg(((const float4*)(X + s0 * NINP)) + q);
        acc.x += w0 * x0.x; acc.y += w0 * x0.y; acc.z += w0 * x0.z; acc.w += w0 * x0.w;
    }
    if (i < end) {
        int2 e1 = __ldg(&g_csrp[i]);
        if (h == 0) {
            float wt = __int_as_float(e1.y);
            float4 x = __ldg(((const float4*)(X + e1.x * NINP)) + q);
            acc.x += wt * x.x; acc.y += wt * x.y; acc.z += wt * x.z; acc.w += wt * x.w;
        }
    }
    // combine halves
    acc.x += __shfl_xor_sync(0xffffffffu, acc.x, 16);
    acc.y += __shfl_xor_sync(0xffffffffu, acc.y, 16);
    acc.z += __shfl_xor_sync(0xffffffffu, acc.z, 16);
    acc.w += __shfl_xor_sync(0xffffffffu, acc.w, 16);
    if (h == 0) {
        float4 xs = __ldg(((const float4*)(X + d * NINP)) + q);
        float sw = dd * dd;
        acc.x = acc.x * dd + sw * xs.x;
        acc.y = acc.y * dd + sw * xs.y;
        acc.z = acc.z * dd + sw * xs.z;
        acc.w = acc.w * dd + sw * xs.w;
        ((float4*)(g_y + d * NINP))[q] = acc;
    }
}

// K8: gather pass 2 — warp per unique token node (fp32 y), packed CSR
__global__ void k_gather2() {
    int w = (int)(((long long)blockIdx.x * blockDim.x + threadIdx.x) >> 5);
    if (w >= g_ntok) return;
    int d = g_toklist[w];
    int lane = threadIdx.x & 31;
    int beg = g_off[d], end = g_cur[d];
    float dd = g_dinv[d];
    float ax = 0.f, ay = 0.f, cw = 0.f;
    int i = beg;
    for (; i + 4 <= end; i += 4) {
        int2 e0 = __ldg(&g_csrp[i]),     e1 = __ldg(&g_csrp[i + 1]);
        int2 e2 = __ldg(&g_csrp[i + 2]), e3 = __ldg(&g_csrp[i + 3]);
        float w0 = __int_as_float(e0.y), w1 = __int_as_float(e1.y);
        float w2 = __int_as_float(e2.y), w3 = __int_as_float(e3.y);
        float2 x0 = ((const float2*)(g_y + e0.x * NINP))[lane];
        float2 x1 = ((const float2*)(g_y + e1.x * NINP))[lane];
        float2 x2 = ((const float2*)(g_y + e2.x * NINP))[lane];
        float2 x3 = ((const float2*)(g_y + e3.x * NINP))[lane];
        ax += w0 * x0.x + w1 * x1.x + w2 * x2.x + w3 * x3.x;
        ay += w0 * x0.y + w1 * x1.y + w2 * x2.y + w3 * x3.y;
        cw += w0 + w1 + w2 + w3;
    }
    for (; i < end; i++) {
        int2 e0 = __ldg(&g_csrp[i]);
        float ww = __int_as_float(e0.y);
        float2 x = ((const float2*)(g_y + e0.x * NINP))[lane];
        ax += ww * x.x; ay += ww * x.y; cw += ww;
    }
    ax *= dd; ay *= dd; cw *= dd;
    float sw = dd * dd;
    float2 ys = ((const float2*)(g_y + d * NINP))[lane];
    ax += sw * ys.x; ay += sw * ys.y; cw += sw;
    ((float2*)(g_z + d * NINP))[lane] = make_float2(ax, ay);
    if (lane == 0) g_c[d] = cw;
}

// K9: W12 = W1@W2, bW = b1@W2
__global__ void k_w12(const float* __restrict__ W1, const float* __restrict__ b1,
                      const float* __restrict__ W2) {
    int j = threadIdx.x;
    int b = blockIdx.x;
    float acc = 0.f;
    if (b < NINP) {
        #pragma unroll 8
        for (int k = 0; k < 2 * NINP; k++) acc += W1[b * 2 * NINP + k] * W2[k * NINP + j];
        g_W12[b * NINP + j] = acc;
    } else {
        #pragma unroll 8
        for (int k = 0; k < 2 * NINP; k++) acc += b1[k] * W2[k * NINP + j];
        g_bW[j] = acc;
    }
}

// K10: out[n,j] = z[tok].W12[:,j] + c[tok]*bW[j] + b2[j]
__global__ void k_out(const void* __restrict__ inp, const float* __restrict__ b2,
                      float* __restrict__ out) {
    __shared__ float sW[NINP * NINP];
    __shared__ float sz[4][NINP];
    __shared__ float sc[4];
    int tid = threadIdx.x;
    int g = tid >> 6;
    int j = tid & 63;
    int n = blockIdx.x * 4 + g;
    int is64 = g_is64;

    for (int i = tid; i < NINP * NINP; i += 256) sW[i] = g_W12[i];
    int tok = (int)ld_idx(inp, n, is64);
    sz[g][j] = g_z[tok * NINP + j];
    if (j == 0) sc[g] = g_c[tok];
    __syncthreads();

    float acc = 0.f;
    #pragma unroll
    for (int i = 0; i < NINP; i++) acc += sz[g][i] * sW[i * NINP + j];
    out[n * NINP + j] = acc + sc[g] * g_bW[j] + b2[j];
}

// ---------------------------------------------------------------------------
extern "C" void kernel_launch(void* const* d_in, const int* in_sizes, int n_in,
                              void* d_out, int out_size) {
    const float* emb = (const float*)d_in[0];
    const float* W1  = (const float*)d_in[1];
    const float* b1  = (const float*)d_in[2];
    const float* W2  = (const float*)d_in[3];
    const float* b2  = (const float*)d_in[4];
    const void*  inp = d_in[5];
    const void*  eidx = d_in[7];
    float* out = (float*)d_out;

    const int TB = 256;
    k_zero<<<(NTOKEN + TB - 1) / TB, TB>>>(eidx);
    k_tokbm<<<(NBL + TB - 1) / TB, TB>>>(inp);
    k_deg<<<(NEDGE / 4 + TB - 1) / TB, TB>>>(eidx);
    k_bsum<<<NB_SCAN, 256>>>();
    k_btop<<<1, 1024>>>();
    k_offs<<<NB_SCAN, 256>>>();
    k_fill<<<(NEDGE / 4 + TB - 1) / TB, TB>>>(eidx);
    k_gather1<<<(NTOKEN * 32 + TB - 1) / TB, TB>>>(emb);
    k_gather2<<<(NBL * 32 + TB - 1) / TB, TB>>>();
    k_w12<<<NINP + 1, NINP>>>(W1, b1, W2);
    k_out<<<NBL / 4, TB>>>(inp, b2, out);
}